// round 16
// baseline (speedup 1.0000x reference)
#include <cuda_runtime.h>
#include <cuda_fp16.h>
#include <cstdint>

// ---------------------------------------------------------------- constants
#define Dm     1024
#define Bsz    8
#define Lw     4096
#define Ssent  255

#define NCHUNK 32            // k chunks of width 32
#define STAGES 3
#define ROWB   80            // smem row stride bytes (32 fp16 + 16B pad)
#define TILE_A (128 * ROWB)  // A tile bytes per stage (BM = 128)

#define SG_BLKS 256          // sentence-GEMM blocks (prefix of mega grid)
#define SM_MAIN (STAGES * (TILE_A + 128 * ROWB))   // 61440
// sentence path uses STAGES * (TILE_A + 64*ROWB) = 46080 <= SM_MAIN

// cvt_all geometry
#define CVW_BLKS 8192        // words blocks
#define CVS_BLKS 510         // sents blocks (510*256*4 float4 = 2040*1024 f32)
#define CVWT_BLKS 1024       // W rows

// ---------------------------------------------------------------- scratch
__device__ __half g_Aw[32768ull * 1024];  // words fp16
__device__ __half g_Wa[1024ull  * 1024];  // W[:, :1024] fp16
__device__ __half g_Wb[1024ull  * 1024];  // W[:, 1024:] fp16
__device__ __half g_Sp[2048ull  * 1024];  // sents fp16 (rows >= 2040 stay 0)
__device__ float  g_Y2[2048ull  * 1024];  // sentence pre-projection
__device__ int    g_done;                 // sentG completion counter

// ---------------------------------------------------------------- PTX utils
__device__ __forceinline__ uint32_t smem_u32(const void* p) {
    uint32_t a;
    asm("{ .reg .u64 t; cvta.to.shared.u64 t, %1; cvt.u32.u64 %0, t; }"
        : "=r"(a) : "l"(p));
    return a;
}
__device__ __forceinline__ void cp16(uint32_t dst, const void* src) {
    asm volatile("cp.async.cg.shared.global [%0], [%1], 16;"
                 :: "r"(dst), "l"(src));
}
#define CP_COMMIT() asm volatile("cp.async.commit_group;" ::: "memory")
#define CP_WAIT(n)  asm volatile("cp.async.wait_group %0;" :: "n"(n) : "memory")

#define LDSM_X4(r, addr) \
    asm volatile("ldmatrix.sync.aligned.m8n8.x4.shared.b16 {%0,%1,%2,%3}, [%4];" \
        : "=r"((r)[0]), "=r"((r)[1]), "=r"((r)[2]), "=r"((r)[3]) : "r"(addr))

__device__ __forceinline__ void mma16816(float* c, const uint32_t* a,
                                         uint32_t b0, uint32_t b1) {
    asm volatile(
        "mma.sync.aligned.m16n8k16.row.col.f32.f16.f16.f32 "
        "{%0,%1,%2,%3}, {%4,%5,%6,%7}, {%8,%9}, {%0,%1,%2,%3};"
        : "+f"(c[0]), "+f"(c[1]), "+f"(c[2]), "+f"(c[3])
        : "r"(a[0]), "r"(a[1]), "r"(a[2]), "r"(a[3]), "r"(b0), "r"(b1));
}

__device__ __forceinline__ uint32_t packh2(float lo, float hi) {
    __half2 h = __float22half2_rn(make_float2(lo, hi));
    return *(uint32_t*)&h;
}

// ---------------------------------------------------------------- cvt_all
// One zero-smem low-reg launch: words + sents + W conversions, flag reset.
__global__ __launch_bounds__(256)
void cvt_all(const float* __restrict__ words,
             const float* __restrict__ sents,
             const float* __restrict__ W1w)
{
    const int tid = threadIdx.x;
    const int b   = blockIdx.x;

    if (b == 0 && tid == 0) g_done = 0;   // reset for this replay

    if (b < CVW_BLKS) {
        // words: 4 front-batched float4 per thread (MLP=4)
        const size_t N = (size_t)CVW_BLKS * 256;
        const size_t t = (size_t)b * 256 + tid;
        const float4* src = (const float4*)words;
        uint2* dst = (uint2*)g_Aw;
        float4 v[4];
        #pragma unroll
        for (int k = 0; k < 4; k++) v[k] = src[t + k * N];
        #pragma unroll
        for (int k = 0; k < 4; k++) {
            uint2 w;
            w.x = packh2(v[k].x, v[k].y);
            w.y = packh2(v[k].z, v[k].w);
            dst[t + k * N] = w;
        }
    } else if (b < CVW_BLKS + CVS_BLKS) {
        // sents: same pattern over 2040*1024 floats
        const int cb = b - CVW_BLKS;
        const size_t N = (size_t)CVS_BLKS * 256;
        const size_t t = (size_t)cb * 256 + tid;
        const float4* src = (const float4*)sents;
        uint2* dst = (uint2*)g_Sp;
        float4 v[4];
        #pragma unroll
        for (int k = 0; k < 4; k++) v[k] = src[t + k * N];
        #pragma unroll
        for (int k = 0; k < 4; k++) {
            uint2 w;
            w.x = packh2(v[k].x, v[k].y);
            w.y = packh2(v[k].z, v[k].w);
            dst[t + k * N] = w;
        }
    } else {
        // W row r -> Wa (cols 0:1024) and Wb (cols 1024:2048)
        const int r = b - CVW_BLKS - CVS_BLKS;
        const int c = tid * 4;
        float4 va = *(const float4*)(W1w + (size_t)r * 2048 + c);
        float4 vb = *(const float4*)(W1w + (size_t)r * 2048 + 1024 + c);
        uint2 aw, bw;
        aw.x = packh2(va.x, va.y); aw.y = packh2(va.z, va.w);
        bw.x = packh2(vb.x, vb.y); bw.y = packh2(vb.z, vb.w);
        *(uint2*)(g_Wa + (size_t)r * 1024 + c) = aw;
        *(uint2*)(g_Wb + (size_t)r * 1024 + c) = bw;
    }
}

// ---------------------------------------------------------------- GEMM body
// Shared mainloop for both paths. QN=2 -> BN=64 (sentence), QN=4 -> BN=128.
template<int QN, bool FUSED>
__device__ __forceinline__
void gemm_body(const __half* __restrict__ Ap,
               const __half* __restrict__ Bp,
               const float*  __restrict__ bias,
               const int*    __restrict__ smap,
               float* __restrict__ out,
               int mStart, int nStart, char* smem_raw)
{
    constexpr int BN     = QN * 32;
    constexpr int TILE_B = BN * ROWB;
    constexpr int STG    = TILE_A + TILE_B;

    const uint32_t base = smem_u32(smem_raw);
    const int tid  = threadIdx.x;
    const int lane = tid & 31;
    const int wid  = tid >> 5;
    const int wm   = wid >> 1;
    const int wn   = wid & 1;

    auto prefetch = [&](int u) {
        const uint32_t st = base + (u % STAGES) * STG;
        const int k0 = u * 32;
        #pragma unroll
        for (int i = 0; i < 2; i++) {
            const int idx = tid + i * 256;
            const int row = idx >> 2, ch = idx & 3;
            cp16(st + row * ROWB + ch * 16,
                 Ap + (size_t)(mStart + row) * 1024 + k0 + ch * 8);
        }
        #pragma unroll
        for (int i = 0; i < QN / 2; i++) {
            const int idx = tid + i * 256;
            const int row = idx >> 2, ch = idx & 3;
            cp16(st + TILE_A + row * ROWB + ch * 16,
                 Bp + (size_t)(nStart + row) * 1024 + k0 + ch * 8);
        }
        CP_COMMIT();
    };

    prefetch(0);
    prefetch(1);

    float acc[2][2 * QN][4];
    #pragma unroll
    for (int mt = 0; mt < 2; mt++)
        #pragma unroll
        for (int nt = 0; nt < 2 * QN; nt++)
            #pragma unroll
            for (int j = 0; j < 4; j++) acc[mt][nt][j] = 0.f;

    const uint32_t aOff = (uint32_t)(wm * 32 + (lane & 15)) * ROWB
                        + ((lane >> 4) * 16);
    const uint32_t bOff = (uint32_t)(wn * (BN / 2) + ((lane >> 4) & 1) * 8 + (lane & 7)) * ROWB
                        + (((lane >> 3) & 1) * 16);

    for (int t = 0; t < NCHUNK; t++) {
        if (t < NCHUNK - 1) CP_WAIT(1); else CP_WAIT(0);
        __syncthreads();

        if (t + 2 < NCHUNK) prefetch(t + 2);

        const uint32_t st = base + (t % STAGES) * STG;
        const uint32_t aS = st + aOff;
        const uint32_t bS = st + TILE_A + bOff;

        #pragma unroll
        for (int kk = 0; kk < 2; kk++) {
            const uint32_t kb = kk * 32;
            uint32_t b[QN][4];
            #pragma unroll
            for (int q = 0; q < QN; q++)
                LDSM_X4(b[q], bS + q * 16 * ROWB + kb);

            uint32_t a[2][4];
            LDSM_X4(a[0], aS + kb);
            LDSM_X4(a[1], aS + 16 * ROWB + kb);

            #pragma unroll
            for (int mt = 0; mt < 2; mt++)
                #pragma unroll
                for (int q = 0; q < QN; q++) {
                    mma16816(acc[mt][2 * q + 0], a[mt], b[q][0], b[q][1]);
                    mma16816(acc[mt][2 * q + 1], a[mt], b[q][2], b[q][3]);
                }
        }
    }

    // ---- FUSED path: wait for sentence GEMM completion before gather
    if (FUSED) {
        if (tid == 0) {
            int v;
            do {
                asm volatile("ld.acquire.gpu.global.b32 %0, [%1];"
                             : "=r"(v) : "l"(&g_done) : "memory");
            } while (v < SG_BLKS);
        }
        __syncthreads();
    }

    const int rBase = mStart + wm * 32 + (lane >> 2);
    const int cBase = nStart + wn * (BN / 2) + (lane & 3) * 2;

    float2 bias2[2 * QN];
    if (FUSED) {
        #pragma unroll
        for (int nt = 0; nt < 2 * QN; nt++)
            bias2[nt] = *(const float2*)(bias + cBase + nt * 8);
    }

    #pragma unroll
    for (int mt = 0; mt < 2; mt++)
        #pragma unroll
        for (int rs = 0; rs < 2; rs++) {
            const int row = rBase + mt * 16 + rs * 8;
            float* op = out + (size_t)row * 1024;

            if (FUSED) {
                const int sv = smap[row];
                const int bb = row >> 12;                  // Lw = 4096
                const float* yrow = g_Y2
                    + (size_t)(bb * Ssent + (sv < 0 ? 0 : sv)) * 1024;
                #pragma unroll
                for (int nt = 0; nt < 2 * QN; nt++) {
                    const int col = cBase + nt * 8;
                    float2 yv = make_float2(0.f, 0.f);
                    if (sv >= 0) yv = *(const float2*)(yrow + col);
                    float2 o;
                    o.x = fmaxf(acc[mt][nt][rs * 2 + 0] + bias2[nt].x + yv.x, 0.f);
                    o.y = fmaxf(acc[mt][nt][rs * 2 + 1] + bias2[nt].y + yv.y, 0.f);
                    *(float2*)(op + col) = o;
                }
            } else {
                #pragma unroll
                for (int nt = 0; nt < 2 * QN; nt++) {
                    const int col = cBase + nt * 8;
                    *(float2*)(op + col) =
                        make_float2(acc[mt][nt][rs * 2 + 0],
                                    acc[mt][nt][rs * 2 + 1]);
                }
            }
        }
}

// ---------------------------------------------------------------- mega kernel
// blocks [0, 256): sentence GEMM Y2 = Sp . Wb^T (BN=64), then flag arrive.
// blocks [256, 2304): main GEMM out = relu(Aw . Wa^T + bias + gather(Y2)),
//   flag-wait before the gather epilogue.
__global__ __launch_bounds__(256, 2)
void mega_gemm(const float* __restrict__ bias,
               const int*   __restrict__ smap,
               float* __restrict__ out)
{
    extern __shared__ char smem_raw[];
    const int b = blockIdx.x;

    if (b < SG_BLKS) {
        const int nStart = (b & 15) * 64;          // 16 n-blocks
        const int mStart = (b >> 4) * 128;         // 16 m-blocks (2048 pad)
        gemm_body<2, false>(g_Sp, g_Wb, nullptr, nullptr,
                            g_Y2, mStart, nStart, smem_raw);
        __threadfence();
        __syncthreads();
        if (threadIdx.x == 0) atomicAdd(&g_done, 1);
    } else {
        const int mb = b - SG_BLKS;
        const int nStart = (mb & 7) * 128;         // N fastest: L2 reuse of A
        const int mStart = (mb >> 3) * 128;
        gemm_body<4, true>(g_Aw, g_Wa, bias, smap,
                           out, mStart, nStart, smem_raw);
    }
}

// ---------------------------------------------------------------- launch
extern "C" void kernel_launch(void* const* d_in, const int* in_sizes, int n_in,
                              void* d_out, int out_size)
{
    const float* words = (const float*)d_in[0];  // [8, 4096, 1024]
    const float* sents = (const float*)d_in[1];  // [8, 255, 1024]
    const float* W1w   = (const float*)d_in[2];  // [1024, 2048]
    const float* W1b   = (const float*)d_in[3];  // [1024]
    const int*   smap  = (const int*)d_in[4];    // [8, 4096]
    float*       out   = (float*)d_out;          // [8, 4096, 1024]

    cudaFuncSetAttribute((const void*)mega_gemm,
                         cudaFuncAttributeMaxDynamicSharedMemorySize, SM_MAIN);

    // Launch 1: all conversions + flag reset (zero smem, high occupancy)
    cvt_all<<<CVW_BLKS + CVS_BLKS + CVWT_BLKS, 256>>>(words, sents, W1w);

    // Launch 2: sentence GEMM (wave-1 prefix) + main GEMM with flag sync
    mega_gemm<<<SG_BLKS + 2048, 256, SM_MAIN>>>(W1b, smap, out);
}

// round 17
// speedup vs baseline: 1.7340x; 1.7340x over previous
#include <cuda_runtime.h>
#include <cuda_fp16.h>
#include <cstdint>

// ---------------------------------------------------------------- constants
#define Dm     1024
#define Bsz    8
#define Lw     4096
#define Ssent  255

#define NCHUNK 32            // k chunks of width 32
#define STAGES 3
#define ROWB   80            // smem row stride bytes (32 fp16 + 16B pad)
#define TILE_A (128 * ROWB)  // A tile bytes per stage (BM = 128 always)

// cvt_all geometry
#define CVW_BLKS  8192       // words blocks
#define CVS_BLKS  510        // sents blocks (510*256*4 float4 = 2040*1024 f32)
#define CVWT_BLKS 1024       // W rows

// ---------------------------------------------------------------- scratch
__device__ __half g_Aw[32768ull * 1024];  // words fp16
__device__ __half g_Wa[1024ull  * 1024];  // W[:, :1024] fp16
__device__ __half g_Wb[1024ull  * 1024];  // W[:, 1024:] fp16
__device__ __half g_Sp[2048ull  * 1024];  // sents fp16 (rows >= 2040 stay 0)
__device__ float  g_Y2[2048ull  * 1024];  // sentence pre-projection

// ---------------------------------------------------------------- PTX utils
__device__ __forceinline__ uint32_t smem_u32(const void* p) {
    uint32_t a;
    asm("{ .reg .u64 t; cvta.to.shared.u64 t, %1; cvt.u32.u64 %0, t; }"
        : "=r"(a) : "l"(p));
    return a;
}
__device__ __forceinline__ void cp16(uint32_t dst, const void* src) {
    asm volatile("cp.async.cg.shared.global [%0], [%1], 16;"
                 :: "r"(dst), "l"(src));
}
#define CP_COMMIT() asm volatile("cp.async.commit_group;" ::: "memory")
#define CP_WAIT(n)  asm volatile("cp.async.wait_group %0;" :: "n"(n) : "memory")

// non-trans ldmatrix: rows hold contiguous k (A rows = m, B rows = n)
#define LDSM_X4(r, addr) \
    asm volatile("ldmatrix.sync.aligned.m8n8.x4.shared.b16 {%0,%1,%2,%3}, [%4];" \
        : "=r"((r)[0]), "=r"((r)[1]), "=r"((r)[2]), "=r"((r)[3]) : "r"(addr))

__device__ __forceinline__ void mma16816(float* c, const uint32_t* a,
                                         uint32_t b0, uint32_t b1) {
    asm volatile(
        "mma.sync.aligned.m16n8k16.row.col.f32.f16.f16.f32 "
        "{%0,%1,%2,%3}, {%4,%5,%6,%7}, {%8,%9}, {%0,%1,%2,%3};"
        : "+f"(c[0]), "+f"(c[1]), "+f"(c[2]), "+f"(c[3])
        : "r"(a[0]), "r"(a[1]), "r"(a[2]), "r"(a[3]), "r"(b0), "r"(b1));
}

__device__ __forceinline__ uint32_t packh2(float lo, float hi) {
    __half2 h = __float22half2_rn(make_float2(lo, hi));
    return *(uint32_t*)&h;
}

// ---------------------------------------------------------------- cvt_all
// One zero-smem, low-reg, high-occupancy launch: words + sents + W conversions.
__global__ __launch_bounds__(256)
void cvt_all(const float* __restrict__ words,
             const float* __restrict__ sents,
             const float* __restrict__ W1w)
{
    const int tid = threadIdx.x;
    const int b   = blockIdx.x;

    if (b < CVW_BLKS) {
        // words: 4 front-batched float4 per thread (MLP=4)
        const size_t N = (size_t)CVW_BLKS * 256;
        const size_t t = (size_t)b * 256 + tid;
        const float4* src = (const float4*)words;
        uint2* dst = (uint2*)g_Aw;
        float4 v[4];
        #pragma unroll
        for (int k = 0; k < 4; k++) v[k] = src[t + k * N];
        #pragma unroll
        for (int k = 0; k < 4; k++) {
            uint2 w;
            w.x = packh2(v[k].x, v[k].y);
            w.y = packh2(v[k].z, v[k].w);
            dst[t + k * N] = w;
        }
    } else if (b < CVW_BLKS + CVS_BLKS) {
        // sents: same pattern over 2040*1024 floats
        const int cb = b - CVW_BLKS;
        const size_t N = (size_t)CVS_BLKS * 256;
        const size_t t = (size_t)cb * 256 + tid;
        const float4* src = (const float4*)sents;
        uint2* dst = (uint2*)g_Sp;
        float4 v[4];
        #pragma unroll
        for (int k = 0; k < 4; k++) v[k] = src[t + k * N];
        #pragma unroll
        for (int k = 0; k < 4; k++) {
            uint2 w;
            w.x = packh2(v[k].x, v[k].y);
            w.y = packh2(v[k].z, v[k].w);
            dst[t + k * N] = w;
        }
    } else {
        // W row r -> Wa (cols 0:1024) and Wb (cols 1024:2048)
        const int r = b - CVW_BLKS - CVS_BLKS;
        const int c = tid * 4;
        float4 va = *(const float4*)(W1w + (size_t)r * 2048 + c);
        float4 vb = *(const float4*)(W1w + (size_t)r * 2048 + 1024 + c);
        uint2 aw, bw;
        aw.x = packh2(va.x, va.y); aw.y = packh2(va.z, va.w);
        bw.x = packh2(vb.x, vb.y); bw.y = packh2(vb.z, vb.w);
        *(uint2*)(g_Wa + (size_t)r * 1024 + c) = aw;
        *(uint2*)(g_Wb + (size_t)r * 1024 + c) = bw;
    }
}

// ---------------------------------------------------------------- GEMM kernel
// (byte-for-byte the round-10 template that measured 210 us / 21.4 us)
// out[m,n] = A[m,:].B[n,:]  (fp16 in, fp32 acc), K = 1024, BM = 128.
// QN: n8-subtile pairs per warp; BN = QN*32 (QN=4 -> BN=128, QN=2 -> BN=64).
// FUSED: + bias + gather(Y2 via smap) + ReLU
template<bool FUSED, int QN>
__global__ __launch_bounds__(256, 2)
void gemm_f16(const __half* __restrict__ Ap,    // pitch 1024
              const __half* __restrict__ Bp,    // pitch 1024
              const float* __restrict__ bias,
              const int*   __restrict__ smap,
              const float* __restrict__ y2,
              float* __restrict__ out)
{
    constexpr int BN     = QN * 32;
    constexpr int TILE_B = BN * ROWB;
    constexpr int STG    = TILE_A + TILE_B;

    extern __shared__ char smem_raw[];
    const uint32_t base = smem_u32(smem_raw);

    const int tid  = threadIdx.x;
    const int lane = tid & 31;
    const int wid  = tid >> 5;
    const int wm   = wid >> 1;             // 0..3 -> M offset wm*32
    const int wn   = wid & 1;              // 0..1 -> N offset wn*(BN/2)
    const int nStart = blockIdx.x * BN;    // N fastest: A block shared via L2
    const int mStart = blockIdx.y * 128;

    // prefetch chunk u: A (128x32) and B (BNx32) fp16 into slot u%3
    auto prefetch = [&](int u) {
        const uint32_t st = base + (u % STAGES) * STG;
        const int k0 = u * 32;
        #pragma unroll
        for (int i = 0; i < 2; i++) {                      // A: 512 tasks
            const int idx = tid + i * 256;
            const int row = idx >> 2, ch = idx & 3;
            cp16(st + row * ROWB + ch * 16,
                 Ap + (size_t)(mStart + row) * 1024 + k0 + ch * 8);
        }
        #pragma unroll
        for (int i = 0; i < QN / 2; i++) {                 // B: BN*4 tasks
            const int idx = tid + i * 256;
            const int row = idx >> 2, ch = idx & 3;
            cp16(st + TILE_A + row * ROWB + ch * 16,
                 Bp + (size_t)(nStart + row) * 1024 + k0 + ch * 8);
        }
        CP_COMMIT();
    };

    prefetch(0);
    prefetch(1);

    float acc[2][2 * QN][4];
    #pragma unroll
    for (int mt = 0; mt < 2; mt++)
        #pragma unroll
        for (int nt = 0; nt < 2 * QN; nt++)
            #pragma unroll
            for (int j = 0; j < 4; j++) acc[mt][nt][j] = 0.f;

    // ldmatrix lane offsets
    // A x4: lanes 0-7 m0-7|k0 , 8-15 m8-15|k0 , 16-23 m0-7|k8 , 24-31 m8-15|k8
    const uint32_t aOff = (uint32_t)(wm * 32 + (lane & 15)) * ROWB
                        + ((lane >> 4) * 16);
    // B x4: lanes 0-7 n0-7|k0 , 8-15 n0-7|k8 , 16-23 n8-15|k0 , 24-31 n8-15|k8
    const uint32_t bOff = (uint32_t)(wn * (BN / 2) + ((lane >> 4) & 1) * 8 + (lane & 7)) * ROWB
                        + (((lane >> 3) & 1) * 16);

    for (int t = 0; t < NCHUNK; t++) {
        if (t < NCHUNK - 1) CP_WAIT(1); else CP_WAIT(0);
        __syncthreads();

        if (t + 2 < NCHUNK) prefetch(t + 2);

        const uint32_t st = base + (t % STAGES) * STG;
        const uint32_t aS = st + aOff;
        const uint32_t bS = st + TILE_A + bOff;

        #pragma unroll
        for (int kk = 0; kk < 2; kk++) {            // two k16 per chunk
            const uint32_t kb = kk * 32;            // 16 fp16 = 32B
            uint32_t b[QN][4];
            #pragma unroll
            for (int q = 0; q < QN; q++)
                LDSM_X4(b[q], bS + q * 16 * ROWB + kb);

            uint32_t a[2][4];
            LDSM_X4(a[0], aS + kb);
            LDSM_X4(a[1], aS + 16 * ROWB + kb);

            #pragma unroll
            for (int mt = 0; mt < 2; mt++)
                #pragma unroll
                for (int q = 0; q < QN; q++) {
                    mma16816(acc[mt][2 * q + 0], a[mt], b[q][0], b[q][1]);
                    mma16816(acc[mt][2 * q + 1], a[mt], b[q][2], b[q][3]);
                }
        }
    }

    // -------- epilogue (register accumulators)
    const int rBase = mStart + wm * 32 + (lane >> 2);
    const int cBase = nStart + wn * (BN / 2) + (lane & 3) * 2;

    float2 bias2[2 * QN];
    if (FUSED) {
        #pragma unroll
        for (int nt = 0; nt < 2 * QN; nt++)
            bias2[nt] = *(const float2*)(bias + cBase + nt * 8);
    }

    #pragma unroll
    for (int mt = 0; mt < 2; mt++) {
        #pragma unroll
        for (int rs = 0; rs < 2; rs++) {
            const int row = rBase + mt * 16 + rs * 8;
            float* op = out + (size_t)row * 1024;

            if (FUSED) {
                const int sv = smap[row];
                const int bb = row >> 12;                  // Lw = 4096
                const float* yrow = y2
                    + (size_t)(bb * Ssent + (sv < 0 ? 0 : sv)) * 1024;
                #pragma unroll
                for (int nt = 0; nt < 2 * QN; nt++) {
                    const int col = cBase + nt * 8;
                    float2 yv = make_float2(0.f, 0.f);
                    if (sv >= 0) yv = *(const float2*)(yrow + col);
                    float2 o;
                    o.x = fmaxf(acc[mt][nt][rs * 2 + 0] + bias2[nt].x + yv.x, 0.f);
                    o.y = fmaxf(acc[mt][nt][rs * 2 + 1] + bias2[nt].y + yv.y, 0.f);
                    *(float2*)(op + col) = o;
                }
            } else {
                #pragma unroll
                for (int nt = 0; nt < 2 * QN; nt++) {
                    const int col = cBase + nt * 8;
                    *(float2*)(op + col) =
                        make_float2(acc[mt][nt][rs * 2 + 0],
                                    acc[mt][nt][rs * 2 + 1]);
                }
            }
        }
    }
}

// ---------------------------------------------------------------- launch
extern "C" void kernel_launch(void* const* d_in, const int* in_sizes, int n_in,
                              void* d_out, int out_size)
{
    const float* words = (const float*)d_in[0];  // [8, 4096, 1024]
    const float* sents = (const float*)d_in[1];  // [8, 255, 1024]
    const float* W1w   = (const float*)d_in[2];  // [1024, 2048]
    const float* W1b   = (const float*)d_in[3];  // [1024]
    const int*   smap  = (const int*)d_in[4];    // [8, 4096]
    float*       out   = (float*)d_out;          // [8, 4096, 1024]

    void *pAw, *pWa, *pWb, *pSp, *pY2;
    cudaGetSymbolAddress(&pAw, g_Aw);
    cudaGetSymbolAddress(&pWa, g_Wa);
    cudaGetSymbolAddress(&pWb, g_Wb);
    cudaGetSymbolAddress(&pSp, g_Sp);
    cudaGetSymbolAddress(&pY2, g_Y2);

    constexpr int SM_MAIN = STAGES * (TILE_A + 128 * ROWB);   // 61440
    constexpr int SM_SENT = STAGES * (TILE_A + 64 * ROWB);    // 46080
    cudaFuncSetAttribute((const void*)gemm_f16<true, 4>,
                         cudaFuncAttributeMaxDynamicSharedMemorySize, SM_MAIN);
    cudaFuncSetAttribute((const void*)gemm_f16<false, 2>,
                         cudaFuncAttributeMaxDynamicSharedMemorySize, SM_SENT);

    // Launch 1: all fp32 -> fp16 conversions in one zero-smem grid
    cvt_all<<<CVW_BLKS + CVS_BLKS + CVWT_BLKS, 256>>>(words, sents, W1w);

    // Launch 2: sentence pre-projection Y2[2048(pad), 1024], BN=64
    dim3 gridS(Dm / 64, 2048 / 128);             // 16 x 16
    gemm_f16<false, 2><<<gridS, 256, SM_SENT>>>(
        (const __half*)pSp, (const __half*)pWb,
        nullptr, nullptr, nullptr, (float*)pY2);

    // Launch 3: main GEMM with fused gather + bias + ReLU, BN=128
    dim3 gridM(Dm / 128, (Bsz * Lw) / 128);      // 8 x 256
    gemm_f16<true, 4><<<gridM, 256, SM_MAIN>>>(
        (const __half*)pAw, (const __half*)pWa,
        W1b, smap, (const float*)pY2, out);
}